// round 6
// baseline (speedup 1.0000x reference)
#include <cuda_runtime.h>
#include <cstdint>

typedef unsigned long long u64;

#define BM  32      // rows per CTA
#define AST 68      // activation row stride in floats (pad: 16B-aligned rows, dup layout)

// ---------------- device scratch (no allocations allowed) ----------------
static __device__ __align__(256) float gW0T[64 * 256];   // [k][j]  = W0[j][k+1]
static __device__ __align__(256) float gW1T[256 * 256];  // [k][j]  = W1[j][k+1]
static __device__ __align__(256) float gW2T[256 * 64];   // [k][j]  = W2[j][k+1]
static __device__ __align__(256) float gW2c[64 * 256];   // [i][j]  = W2[i][j+1]
static __device__ __align__(256) float gW1c[256 * 256];  // [i][j]  = W1[i][j+1]
static __device__ __align__(256) float gW0c[256 * 64];   // [j][k]  = W0[j][k+1]
static __device__ __align__(256) float gB0[256];
static __device__ __align__(256) float gB1[256];
static __device__ __align__(256) float gB2[64];

// ---------------- prep: transpose/compact weights, fold t into bias ----------------
__global__ void prep_kernel(const float* __restrict__ t,
                            const float* __restrict__ W0, const float* __restrict__ b0,
                            const float* __restrict__ W1, const float* __restrict__ b1,
                            const float* __restrict__ W2, const float* __restrict__ b2)
{
    int b = blockIdx.x;   // 0..255
    int x = threadIdx.x;  // 0..255
    gW1T[b * 256 + x] = W1[x * 257 + b + 1];
    gW1c[b * 256 + x] = W1[b * 257 + x + 1];
    if (b < 64) {
        gW0T[b * 256 + x] = W0[x * 65 + b + 1];
        gW2c[b * 256 + x] = W2[b * 257 + x + 1];
    }
    if (x < 64) {
        gW2T[b * 64 + x] = W2[x * 257 + b + 1];
        gW0c[b * 64 + x] = W0[b * 65 + x + 1];
    }
    if (b == 0) {
        float tv = t[0];
        gB0[x] = b0[x] + tv * W0[x * 65];
        gB1[x] = b1[x] + tv * W1[x * 257];
        if (x < 64) gB2[x] = b2[x] + tv * W2[x * 257];
    }
}

// ---------------- helpers ----------------
__device__ __forceinline__ void fma2(u64& c, u64 a, u64 b) {
    asm volatile("fma.rn.f32x2 %0, %1, %2, %0;" : "+l"(c) : "l"(a), "l"(b));
}
__device__ __forceinline__ u64 pack2(float x, float y) {
    u64 r; asm("mov.b64 %0, {%1, %2};" : "=l"(r) : "f"(x), "f"(y)); return r;
}
__device__ __forceinline__ float2 unpk2(u64 v) {
    float2 f; asm("mov.b64 {%0, %1}, %2;" : "=f"(f.x), "=f"(f.y) : "l"(v)); return f;
}
__device__ __forceinline__ void cp16(uint32_t s, const void* g) {
    asm volatile("cp.async.cg.shared.global [%0], [%1], 16;" :: "r"(s), "l"(g));
}
__device__ __forceinline__ void cpcommit() { asm volatile("cp.async.commit_group;"); }
__device__ __forceinline__ void cpwait0()  { asm volatile("cp.async.wait_group 0;"); }
__device__ __forceinline__ void cpwait1()  { asm volatile("cp.async.wait_group 1;"); }

__device__ __forceinline__ void actf(float z, float& s, float& h) {
    // sigmoid + softplus (matches jax.nn.softplus = max(z,0)+log1p(exp(-|z|)))
    float ea  = __expf(-fabsf(z));
    float inv = __fdividef(1.f, 1.f + ea);
    s = (z >= 0.f) ? inv : ea * inv;
    h = fmaxf(z, 0.f) + __logf(1.f + ea);
}

// ---------------- GEMM A: out[32][256] += in[32][K] @ W[K][256] ----------------
// thread map: rowg=tid>>6 (8 rows), colg=tid&63 (col pairs j0=2*colg and j0+128)
template<int KK>
__device__ __forceinline__ void gemmA(const float* __restrict__ gW, const float* sIn,
                                      float* wbuf, u64 acc[8][2], int tid)
{
    const int rowg = tid >> 6, colg = tid & 63;
    const int m2 = rowg * 16;      // 2*m0
    const int jo = colg * 2;
    constexpr int C = KK / 32;
    uint32_t wsh = (uint32_t)__cvta_generic_to_shared(wbuf);
    {
        uint32_t s = wsh + tid * 16;
        const char* g = (const char*)gW + tid * 16;
#pragma unroll
        for (int i = 0; i < 8; i++) cp16(s + i * 4096, g + i * 4096);
        cpcommit();
    }
#pragma unroll 1
    for (int c = 0; c < C; c++) {
        if (c + 1 < C) {
            uint32_t s = wsh + ((c + 1) & 1) * 32768u + tid * 16;
            const char* g = (const char*)gW + (size_t)(c + 1) * 32768 + tid * 16;
#pragma unroll
            for (int i = 0; i < 8; i++) cp16(s + i * 4096, g + i * 4096);
            cpcommit();
            cpwait1();
        } else {
            cpwait0();
        }
        __syncthreads();
        const float* wb = wbuf + (c & 1) * 8192;
        const float* ip = sIn + c * 32 * AST + m2;
#pragma unroll
        for (int kk = 0; kk < 32; kk++) {
            u64 w0 = *(const u64*)(wb + kk * 256 + jo);
            u64 w1 = *(const u64*)(wb + kk * 256 + jo + 128);
            const float* ar = ip + kk * AST;
#pragma unroll
            for (int rp = 0; rp < 4; rp++) {
                ulonglong2 aa = *(const ulonglong2*)(ar + rp * 4);
                fma2(acc[2 * rp][0],     aa.x, w0);
                fma2(acc[2 * rp][1],     aa.x, w1);
                fma2(acc[2 * rp + 1][0], aa.y, w0);
                fma2(acc[2 * rp + 1][1], aa.y, w1);
            }
        }
        __syncthreads();
    }
}

// ---------------- GEMM B: out[32][64] += in[32][K] @ W[K][64] ----------------
// thread map: rowg=tid>>5 (4 rows), colg=tid&31 (col pair jB=2*colg)
template<int KK>
__device__ __forceinline__ void gemmB(const float* __restrict__ gW, const float* sIn,
                                      float* wbuf, u64 acc[4], int tid)
{
    const int rowg = tid >> 5, colg = tid & 31;
    const int m2 = rowg * 8;       // 2*m0
    const int jo = colg * 2;
    constexpr int C = KK / 32;
    uint32_t wsh = (uint32_t)__cvta_generic_to_shared(wbuf);
    {
        uint32_t s = wsh + tid * 16;
        const char* g = (const char*)gW + tid * 16;
        cp16(s, g); cp16(s + 4096, g + 4096);
        cpcommit();
    }
#pragma unroll 1
    for (int c = 0; c < C; c++) {
        if (c + 1 < C) {
            uint32_t s = wsh + ((c + 1) & 1) * 8192u + tid * 16;
            const char* g = (const char*)gW + (size_t)(c + 1) * 8192 + tid * 16;
            cp16(s, g); cp16(s + 4096, g + 4096);
            cpcommit();
            cpwait1();
        } else {
            cpwait0();
        }
        __syncthreads();
        const float* wb = wbuf + (c & 1) * 2048;
        const float* ip = sIn + c * 32 * AST + m2;
#pragma unroll
        for (int kk = 0; kk < 32; kk++) {
            u64 w = *(const u64*)(wb + kk * 64 + jo);
            const float* ar = ip + kk * AST;
            ulonglong2 aa = *(const ulonglong2*)(ar);
            ulonglong2 ab = *(const ulonglong2*)(ar + 4);
            fma2(acc[0], aa.x, w);
            fma2(acc[1], aa.y, w);
            fma2(acc[2], ab.x, w);
            fma2(acc[3], ab.y, w);
        }
        __syncthreads();
    }
}

// ---------------- main fused kernel ----------------
// smem: X[256][AST], Y[256][AST], E[64][AST], WB[2][8192]
#define SMEM_FLOATS (2 * 256 * AST + 64 * AST + 2 * 8192)
#define SMEM_BYTES  (SMEM_FLOATS * 4)

__global__ void __launch_bounds__(256, 1)
odefunc_kernel(const float* __restrict__ y, const float* __restrict__ e,
               float* __restrict__ out)
{
    extern __shared__ float sm[];
    float* X  = sm;
    float* Y  = sm + 256 * AST;
    float* E  = sm + 2 * 256 * AST;
    float* WB = sm + 2 * 256 * AST + 64 * AST;
    const int tid = threadIdx.x;
    const size_t r0 = (size_t)blockIdx.x * BM;

    // stage y (first 64 cols) and e into duplicated act layout
#pragma unroll
    for (int i = 0; i < 8; i++) {
        int idx = tid + i * 256;            // 0..2047
        int m = idx >> 6, k = idx & 63;
        float v  = y[(r0 + m) * 65 + k];
        X[k * AST + 2 * m] = v;  X[k * AST + 2 * m + 1] = v;
        float ev = e[(r0 + m) * 64 + k];
        E[k * AST + 2 * m] = ev; E[k * AST + 2 * m + 1] = ev;
    }
    // (first barrier inside gemmA orders these writes vs reads)

    const int rowgA = tid >> 6, colgA = tid & 63;
    const int j0 = colgA * 2;
    const int mA = rowgA * 8;
    u64 acc[8][2], s0[8][2], s1[8][2];

    // ---- L0: z0 = in0 @ W0T + beff0 ----
    {
        u64 bA = pack2(gB0[j0], gB0[j0 + 1]);
        u64 bB = pack2(gB0[j0 + 128], gB0[j0 + 129]);
#pragma unroll
        for (int r = 0; r < 8; r++) { acc[r][0] = bA; acc[r][1] = bB; }
    }
    gemmA<64>(gW0T, X, WB, acc, tid);
#pragma unroll
    for (int r = 0; r < 8; r++)
#pragma unroll
        for (int p = 0; p < 2; p++) {
            float2 z = unpk2(acc[r][p]);
            float sx, sy, hx, hy;
            actf(z.x, sx, hx); actf(z.y, sy, hy);
            s0[r][p] = pack2(sx, sy);
            int j = j0 + p * 128;
            int m = mA + r;
            *(u64*)(Y + j * AST + 2 * m)       = pack2(hx, hx);
            *(u64*)(Y + (j + 1) * AST + 2 * m) = pack2(hy, hy);
        }

    // ---- L1: z1 = h0 @ W1T + beff1 ----
    {
        u64 bA = pack2(gB1[j0], gB1[j0 + 1]);
        u64 bB = pack2(gB1[j0 + 128], gB1[j0 + 129]);
#pragma unroll
        for (int r = 0; r < 8; r++) { acc[r][0] = bA; acc[r][1] = bB; }
    }
    gemmA<256>(gW1T, Y, WB, acc, tid);
#pragma unroll
    for (int r = 0; r < 8; r++)
#pragma unroll
        for (int p = 0; p < 2; p++) {
            float2 z = unpk2(acc[r][p]);
            float sx, sy, hx, hy;
            actf(z.x, sx, hx); actf(z.y, sy, hy);
            s1[r][p] = pack2(sx, sy);
            int j = j0 + p * 128;
            int m = mA + r;
            *(u64*)(X + j * AST + 2 * m)       = pack2(hx, hx);
            *(u64*)(X + (j + 1) * AST + 2 * m) = pack2(hy, hy);
        }

    // ---- L2: dx = h1 @ W2T + beff2 ----
    const int rowgB = tid >> 5, colgB = tid & 31;
    const int jB = colgB * 2, mB = rowgB * 4;
    u64 accB[4];
    {
        u64 bb = pack2(gB2[jB], gB2[jB + 1]);
#pragma unroll
        for (int r = 0; r < 4; r++) accB[r] = bb;
    }
    gemmB<256>(gW2T, X, WB, accB, tid);
#pragma unroll
    for (int r = 0; r < 4; r++) {
        float2 dv = unpk2(accB[r]);
        size_t o = (r0 + mB + r) * 65 + jB;
        out[o] = dv.x; out[o + 1] = dv.y;
    }

    // ---- B2: gh1 = e @ W2c ; g1 = gh1 * sigmoid(z1) ----
#pragma unroll
    for (int r = 0; r < 8; r++) { acc[r][0] = 0ull; acc[r][1] = 0ull; }
    gemmA<64>(gW2c, E, WB, acc, tid);
#pragma unroll
    for (int r = 0; r < 8; r++)
#pragma unroll
        for (int p = 0; p < 2; p++) {
            float2 g = unpk2(acc[r][p]);
            float2 s = unpk2(s1[r][p]);
            g.x *= s.x; g.y *= s.y;
            int j = j0 + p * 128;
            int m = mA + r;
            *(u64*)(X + j * AST + 2 * m)       = pack2(g.x, g.x);
            *(u64*)(X + (j + 1) * AST + 2 * m) = pack2(g.y, g.y);
        }

    // ---- B1: gh0 = g1 @ W1c ; g0 = gh0 * sigmoid(z0) ----
#pragma unroll
    for (int r = 0; r < 8; r++) { acc[r][0] = 0ull; acc[r][1] = 0ull; }
    gemmA<256>(gW1c, X, WB, acc, tid);
#pragma unroll
    for (int r = 0; r < 8; r++)
#pragma unroll
        for (int p = 0; p < 2; p++) {
            float2 g = unpk2(acc[r][p]);
            float2 s = unpk2(s0[r][p]);
            g.x *= s.x; g.y *= s.y;
            int j = j0 + p * 128;
            int m = mA + r;
            *(u64*)(Y + j * AST + 2 * m)       = pack2(g.x, g.x);
            *(u64*)(Y + (j + 1) * AST + 2 * m) = pack2(g.y, g.y);
        }

    // ---- B0: edz = g0 @ W0c ; div = sum(edz * e) ----
#pragma unroll
    for (int r = 0; r < 4; r++) accB[r] = 0ull;
    gemmB<256>(gW0c, Y, WB, accB, tid);
#pragma unroll
    for (int r = 0; r < 4; r++) {
        int m = mB + r;
        float2 ez = unpk2(accB[r]);
        float ex = E[jB * AST + 2 * m];
        float ey = E[(jB + 1) * AST + 2 * m];
        float part = ez.x * ex + ez.y * ey;
#pragma unroll
        for (int off = 16; off; off >>= 1)
            part += __shfl_xor_sync(0xffffffffu, part, off);
        if (colgB == 0) out[(r0 + m) * 65 + 64] = -part;
    }
}

// ---------------- launch ----------------
extern "C" void kernel_launch(void* const* d_in, const int* in_sizes, int n_in,
                              void* d_out, int out_size)
{
    const float* t  = (const float*)d_in[0];
    const float* y  = (const float*)d_in[1];
    const float* e  = (const float*)d_in[2];
    const float* W0 = (const float*)d_in[3];
    const float* b0 = (const float*)d_in[4];
    const float* W1 = (const float*)d_in[5];
    const float* b1 = (const float*)d_in[6];
    const float* W2 = (const float*)d_in[7];
    const float* b2 = (const float*)d_in[8];
    float* out = (float*)d_out;
    int B = in_sizes[1] / 65;

    // opt-in to >48KB dynamic smem; skip during capture (attribute persists)
    cudaStreamCaptureStatus cs = cudaStreamCaptureStatusNone;
    cudaStreamIsCapturing((cudaStream_t)0, &cs);
    if (cs == cudaStreamCaptureStatusNone) {
        cudaFuncSetAttribute(odefunc_kernel,
                             cudaFuncAttributeMaxDynamicSharedMemorySize, SMEM_BYTES);
    }

    prep_kernel<<<256, 256>>>(t, W0, b0, W1, b1, W2, b2);
    odefunc_kernel<<<B / BM, 256, SMEM_BYTES>>>(y, e, out);
}

// round 7
// speedup vs baseline: 1.0537x; 1.0537x over previous
#include <cuda_runtime.h>
#include <cstdint>

typedef unsigned long long u64;

#define BM  32      // rows per CTA
#define AST 68      // activation row stride in floats (pad: 16B-aligned rows, dup layout)

// ---------------- device scratch (no allocations allowed) ----------------
static __device__ __align__(256) float gW0T[64 * 256];   // [k][j]  = W0[j][k+1]
static __device__ __align__(256) float gW1T[256 * 256];  // [k][j]  = W1[j][k+1]
static __device__ __align__(256) float gW2T[256 * 64];   // [k][j]  = W2[j][k+1]
static __device__ __align__(256) float gW2c[64 * 256];   // [i][j]  = W2[i][j+1]
static __device__ __align__(256) float gW1c[256 * 256];  // [i][j]  = W1[i][j+1]
static __device__ __align__(256) float gW0c[256 * 64];   // [j][k]  = W0[j][k+1]
static __device__ __align__(256) float gB0[256];
static __device__ __align__(256) float gB1[256];
static __device__ __align__(256) float gB2[64];

// ---------------- prep: transpose/compact weights, fold t into bias ----------------
__global__ void prep_kernel(const float* __restrict__ t,
                            const float* __restrict__ W0, const float* __restrict__ b0,
                            const float* __restrict__ W1, const float* __restrict__ b1,
                            const float* __restrict__ W2, const float* __restrict__ b2)
{
    int b = blockIdx.x;   // 0..255
    int x = threadIdx.x;  // 0..255
    gW1T[b * 256 + x] = W1[x * 257 + b + 1];
    gW1c[b * 256 + x] = W1[b * 257 + x + 1];
    if (b < 64) {
        gW0T[b * 256 + x] = W0[x * 65 + b + 1];
        gW2c[b * 256 + x] = W2[b * 257 + x + 1];
    }
    if (x < 64) {
        gW2T[b * 64 + x] = W2[x * 257 + b + 1];
        gW0c[b * 64 + x] = W0[b * 65 + x + 1];
    }
    if (b == 0) {
        float tv = t[0];
        gB0[x] = b0[x] + tv * W0[x * 65];
        gB1[x] = b1[x] + tv * W1[x * 257];
        if (x < 64) gB2[x] = b2[x] + tv * W2[x * 257];
    }
}

// ---------------- helpers ----------------
__device__ __forceinline__ void fma2(u64& c, u64 a, u64 b) {
    asm volatile("fma.rn.f32x2 %0, %1, %2, %0;" : "+l"(c) : "l"(a), "l"(b));
}
__device__ __forceinline__ u64 pack2(float x, float y) {
    u64 r; asm("mov.b64 %0, {%1, %2};" : "=l"(r) : "f"(x), "f"(y)); return r;
}
__device__ __forceinline__ float2 unpk2(u64 v) {
    float2 f; asm("mov.b64 {%0, %1}, %2;" : "=f"(f.x), "=f"(f.y) : "l"(v)); return f;
}
__device__ __forceinline__ void cp16(uint32_t s, const void* g) {
    asm volatile("cp.async.cg.shared.global [%0], [%1], 16;" :: "r"(s), "l"(g));
}
__device__ __forceinline__ void cpcommit() { asm volatile("cp.async.commit_group;"); }
__device__ __forceinline__ void cpwait0()  { asm volatile("cp.async.wait_group 0;"); }
__device__ __forceinline__ void cpwait1()  { asm volatile("cp.async.wait_group 1;"); }

__device__ __forceinline__ void actf(float z, float& s, float& h) {
    // sigmoid + softplus (matches jax.nn.softplus = max(z,0)+log1p(exp(-|z|)))
    float ea  = __expf(-fabsf(z));
    float inv = __fdividef(1.f, 1.f + ea);
    s = (z >= 0.f) ? inv : ea * inv;
    h = fmaxf(z, 0.f) + __logf(1.f + ea);
}

// ---------------- GEMM A: out[32][256] += in[32][K] @ W[K][256] ----------------
// thread map: rowg=tid>>6 (8 rows), colg=tid&63 (col pairs j0=2*colg and j0+128)
template<int KK>
__device__ __forceinline__ void gemmA(const float* __restrict__ gW, const float* sIn,
                                      float* wbuf, u64 acc[8][2], int tid)
{
    const int rowg = tid >> 6, colg = tid & 63;
    const int m2 = rowg * 16;      // 2*m0
    const int jo = colg * 2;
    constexpr int C = KK / 32;
    uint32_t wsh = (uint32_t)__cvta_generic_to_shared(wbuf);
    {
        uint32_t s = wsh + tid * 16;
        const char* g = (const char*)gW + tid * 16;
#pragma unroll
        for (int i = 0; i < 8; i++) cp16(s + i * 4096, g + i * 4096);
        cpcommit();
    }
#pragma unroll 1
    for (int c = 0; c < C; c++) {
        if (c + 1 < C) {
            uint32_t s = wsh + ((c + 1) & 1) * 32768u + tid * 16;
            const char* g = (const char*)gW + (size_t)(c + 1) * 32768 + tid * 16;
#pragma unroll
            for (int i = 0; i < 8; i++) cp16(s + i * 4096, g + i * 4096);
            cpcommit();
            cpwait1();
        } else {
            cpwait0();
        }
        __syncthreads();
        const float* wb = wbuf + (c & 1) * 8192;
        const float* ip = sIn + c * 32 * AST + m2;
#pragma unroll
        for (int kk = 0; kk < 32; kk++) {
            u64 w0 = *(const u64*)(wb + kk * 256 + jo);
            u64 w1 = *(const u64*)(wb + kk * 256 + jo + 128);
            const float* ar = ip + kk * AST;
#pragma unroll
            for (int rp = 0; rp < 4; rp++) {
                ulonglong2 aa = *(const ulonglong2*)(ar + rp * 4);
                fma2(acc[2 * rp][0],     aa.x, w0);
                fma2(acc[2 * rp][1],     aa.x, w1);
                fma2(acc[2 * rp + 1][0], aa.y, w0);
                fma2(acc[2 * rp + 1][1], aa.y, w1);
            }
        }
        __syncthreads();
    }
}

// ---------------- GEMM B: out[32][64] += in[32][K] @ W[K][64] ----------------
// thread map: rowg=tid>>5 (4 rows), colg=tid&31 (col pair jB=2*colg)
template<int KK>
__device__ __forceinline__ void gemmB(const float* __restrict__ gW, const float* sIn,
                                      float* wbuf, u64 acc[4], int tid)
{
    const int rowg = tid >> 5, colg = tid & 31;
    const int m2 = rowg * 8;       // 2*m0
    const int jo = colg * 2;
    constexpr int C = KK / 32;
    uint32_t wsh = (uint32_t)__cvta_generic_to_shared(wbuf);
    {
        uint32_t s = wsh + tid * 16;
        const char* g = (const char*)gW + tid * 16;
        cp16(s, g); cp16(s + 4096, g + 4096);
        cpcommit();
    }
#pragma unroll 1
    for (int c = 0; c < C; c++) {
        if (c + 1 < C) {
            uint32_t s = wsh + ((c + 1) & 1) * 8192u + tid * 16;
            const char* g = (const char*)gW + (size_t)(c + 1) * 8192 + tid * 16;
            cp16(s, g); cp16(s + 4096, g + 4096);
            cpcommit();
            cpwait1();
        } else {
            cpwait0();
        }
        __syncthreads();
        const float* wb = wbuf + (c & 1) * 2048;
        const float* ip = sIn + c * 32 * AST + m2;
#pragma unroll
        for (int kk = 0; kk < 32; kk++) {
            u64 w = *(const u64*)(wb + kk * 64 + jo);
            const float* ar = ip + kk * AST;
            ulonglong2 aa = *(const ulonglong2*)(ar);
            ulonglong2 ab = *(const ulonglong2*)(ar + 4);
            fma2(acc[0], aa.x, w);
            fma2(acc[1], aa.y, w);
            fma2(acc[2], ab.x, w);
            fma2(acc[3], ab.y, w);
        }
        __syncthreads();
    }
}

// ---------------- main fused kernel ----------------
// smem: X[256][AST], Y[256][AST], E[64][AST], WB[2][8192]
#define SMEM_FLOATS (2 * 256 * AST + 64 * AST + 2 * 8192)
#define SMEM_BYTES  (SMEM_FLOATS * 4)

__global__ void __launch_bounds__(256, 1)
odefunc_kernel(const float* __restrict__ y, const float* __restrict__ e,
               float* __restrict__ out)
{
    extern __shared__ float sm[];
    float* X  = sm;
    float* Y  = sm + 256 * AST;
    float* E  = sm + 2 * 256 * AST;
    float* WB = sm + 2 * 256 * AST + 64 * AST;
    const int tid = threadIdx.x;
    const size_t r0 = (size_t)blockIdx.x * BM;

    // stage y (first 64 cols) and e into duplicated act layout
#pragma unroll
    for (int i = 0; i < 8; i++) {
        int idx = tid + i * 256;            // 0..2047
        int m = idx >> 6, k = idx & 63;
        float v  = y[(r0 + m) * 65 + k];
        X[k * AST + 2 * m] = v;  X[k * AST + 2 * m + 1] = v;
        float ev = e[(r0 + m) * 64 + k];
        E[k * AST + 2 * m] = ev; E[k * AST + 2 * m + 1] = ev;
    }
    // (first barrier inside gemmA orders these writes vs reads)

    const int rowgA = tid >> 6, colgA = tid & 63;
    const int j0 = colgA * 2;
    const int mA = rowgA * 8;
    u64 acc[8][2], s0[8][2], s1[8][2];

    // ---- L0: z0 = in0 @ W0T + beff0 ----
    {
        u64 bA = pack2(gB0[j0], gB0[j0 + 1]);
        u64 bB = pack2(gB0[j0 + 128], gB0[j0 + 129]);
#pragma unroll
        for (int r = 0; r < 8; r++) { acc[r][0] = bA; acc[r][1] = bB; }
    }
    gemmA<64>(gW0T, X, WB, acc, tid);
#pragma unroll
    for (int r = 0; r < 8; r++)
#pragma unroll
        for (int p = 0; p < 2; p++) {
            float2 z = unpk2(acc[r][p]);
            float sx, sy, hx, hy;
            actf(z.x, sx, hx); actf(z.y, sy, hy);
            s0[r][p] = pack2(sx, sy);
            int j = j0 + p * 128;
            int m = mA + r;
            *(u64*)(Y + j * AST + 2 * m)       = pack2(hx, hx);
            *(u64*)(Y + (j + 1) * AST + 2 * m) = pack2(hy, hy);
        }

    // ---- L1: z1 = h0 @ W1T + beff1 ----
    {
        u64 bA = pack2(gB1[j0], gB1[j0 + 1]);
        u64 bB = pack2(gB1[j0 + 128], gB1[j0 + 129]);
#pragma unroll
        for (int r = 0; r < 8; r++) { acc[r][0] = bA; acc[r][1] = bB; }
    }
    gemmA<256>(gW1T, Y, WB, acc, tid);
#pragma unroll
    for (int r = 0; r < 8; r++)
#pragma unroll
        for (int p = 0; p < 2; p++) {
            float2 z = unpk2(acc[r][p]);
            float sx, sy, hx, hy;
            actf(z.x, sx, hx); actf(z.y, sy, hy);
            s1[r][p] = pack2(sx, sy);
            int j = j0 + p * 128;
            int m = mA + r;
            *(u64*)(X + j * AST + 2 * m)       = pack2(hx, hx);
            *(u64*)(X + (j + 1) * AST + 2 * m) = pack2(hy, hy);
        }

    // ---- L2: dx = h1 @ W2T + beff2 ----
    const int rowgB = tid >> 5, colgB = tid & 31;
    const int jB = colgB * 2, mB = rowgB * 4;
    u64 accB[4];
    {
        u64 bb = pack2(gB2[jB], gB2[jB + 1]);
#pragma unroll
        for (int r = 0; r < 4; r++) accB[r] = bb;
    }
    gemmB<256>(gW2T, X, WB, accB, tid);
#pragma unroll
    for (int r = 0; r < 4; r++) {
        float2 dv = unpk2(accB[r]);
        size_t o = (r0 + mB + r) * 65 + jB;
        out[o] = dv.x; out[o + 1] = dv.y;
    }

    // ---- B2: gh1 = e @ W2c ; g1 = gh1 * sigmoid(z1) ----
#pragma unroll
    for (int r = 0; r < 8; r++) { acc[r][0] = 0ull; acc[r][1] = 0ull; }
    gemmA<64>(gW2c, E, WB, acc, tid);
#pragma unroll
    for (int r = 0; r < 8; r++)
#pragma unroll
        for (int p = 0; p < 2; p++) {
            float2 g = unpk2(acc[r][p]);
            float2 s = unpk2(s1[r][p]);
            g.x *= s.x; g.y *= s.y;
            int j = j0 + p * 128;
            int m = mA + r;
            *(u64*)(X + j * AST + 2 * m)       = pack2(g.x, g.x);
            *(u64*)(X + (j + 1) * AST + 2 * m) = pack2(g.y, g.y);
        }

    // ---- B1: gh0 = g1 @ W1c ; g0 = gh0 * sigmoid(z0) ----
#pragma unroll
    for (int r = 0; r < 8; r++) { acc[r][0] = 0ull; acc[r][1] = 0ull; }
    gemmA<256>(gW1c, X, WB, acc, tid);
#pragma unroll
    for (int r = 0; r < 8; r++)
#pragma unroll
        for (int p = 0; p < 2; p++) {
            float2 g = unpk2(acc[r][p]);
            float2 s = unpk2(s0[r][p]);
            g.x *= s.x; g.y *= s.y;
            int j = j0 + p * 128;
            int m = mA + r;
            *(u64*)(Y + j * AST + 2 * m)       = pack2(g.x, g.x);
            *(u64*)(Y + (j + 1) * AST + 2 * m) = pack2(g.y, g.y);
        }

    // ---- B0: edz = g0 @ W0c ; div = sum(edz * e) ----
#pragma unroll
    for (int r = 0; r < 4; r++) accB[r] = 0ull;
    gemmB<256>(gW0c, Y, WB, accB, tid);
#pragma unroll
    for (int r = 0; r < 4; r++) {
        int m = mB + r;
        float2 ez = unpk2(accB[r]);
        float ex = E[jB * AST + 2 * m];
        float ey = E[(jB + 1) * AST + 2 * m];
        float part = ez.x * ex + ez.y * ey;
#pragma unroll
        for (int off = 16; off; off >>= 1)
            part += __shfl_xor_sync(0xffffffffu, part, off);
        if (colgB == 0) out[(r0 + m) * 65 + 64] = -part;
    }
}

// ---------------- launch ----------------
extern "C" void kernel_launch(void* const* d_in, const int* in_sizes, int n_in,
                              void* d_out, int out_size)
{
    const float* t  = (const float*)d_in[0];
    const float* y  = (const float*)d_in[1];
    const float* e  = (const float*)d_in[2];
    const float* W0 = (const float*)d_in[3];
    const float* b0 = (const float*)d_in[4];
    const float* W1 = (const float*)d_in[5];
    const float* b1 = (const float*)d_in[6];
    const float* W2 = (const float*)d_in[7];
    const float* b2 = (const float*)d_in[8];
    float* out = (float*)d_out;
    int B = in_sizes[1] / 65;

    // opt-in to >48KB dynamic smem; skip during capture (attribute persists)
    cudaStreamCaptureStatus cs = cudaStreamCaptureStatusNone;
    cudaStreamIsCapturing((cudaStream_t)0, &cs);
    if (cs == cudaStreamCaptureStatusNone) {
        cudaFuncSetAttribute(odefunc_kernel,
                             cudaFuncAttributeMaxDynamicSharedMemorySize, SMEM_BYTES);
    }

    prep_kernel<<<256, 256>>>(t, W0, b0, W1, b1, W2, b2);
    odefunc_kernel<<<B / BM, 256, SMEM_BYTES>>>(y, e, out);
}

// round 9
// speedup vs baseline: 2.2793x; 2.1632x over previous
#include <cuda_runtime.h>
#include <cuda_bf16.h>
#include <cstdint>
typedef uint32_t u32;

// ---- smem byte map: A_hi[0,64K) A_lo[64K,128K) Wbuf[131072,+2x40960) bias, div ----
#define ALO    65536u
#define WOFF   131072u
#define BIOFF  212992u
#define DIVOFF 215296u
#define SMEMSZ 219392u

// 18 ldmatrix-ready weight chunk images: L0 2x40960, L1 8x40960, L2 8x10240
static __device__ __align__(16) unsigned char gImg[491520];
static __device__ float gBias[576];

__global__ void prep_kernel(const float* __restrict__ t,
                            const float* __restrict__ W0, const float* __restrict__ b0,
                            const float* __restrict__ W1, const float* __restrict__ b1,
                            const float* __restrict__ W2, const float* __restrict__ b2)
{
    int n = blockIdx.x, x = threadIdx.x;         // n: out-neuron, x: k
    {   // W1 [256][257]: chunks of 32 k, rows padded to 80B, hi then lo plane
        float v = W1[n * 257 + x + 1];
        __nv_bfloat16 h = __float2bfloat16(v);
        __nv_bfloat16 l = __float2bfloat16(v - __bfloat162float(h));
        u32 off = 81920u + (u32)(x >> 5) * 40960u + n * 80u + (x & 31) * 2u;
        *(__nv_bfloat16*)(gImg + off) = h;
        *(__nv_bfloat16*)(gImg + off + 20480u) = l;
    }
    if (x < 64) {   // W0 [256][65], K=64 -> 2 chunks
        float v = W0[n * 65 + x + 1];
        __nv_bfloat16 h = __float2bfloat16(v);
        __nv_bfloat16 l = __float2bfloat16(v - __bfloat162float(h));
        u32 off = (u32)(x >> 5) * 40960u + n * 80u + (x & 31) * 2u;
        *(__nv_bfloat16*)(gImg + off) = h;
        *(__nv_bfloat16*)(gImg + off + 20480u) = l;
    }
    if (n < 64) {   // W2 [64][257], 64 rows -> 8 chunks of 10240
        float v = W2[n * 257 + x + 1];
        __nv_bfloat16 h = __float2bfloat16(v);
        __nv_bfloat16 l = __float2bfloat16(v - __bfloat162float(h));
        u32 off = 409600u + (u32)(x >> 5) * 10240u + n * 80u + (x & 31) * 2u;
        *(__nv_bfloat16*)(gImg + off) = h;
        *(__nv_bfloat16*)(gImg + off + 5120u) = l;
    }
    if (n == 0) {
        float tv = t[0];
        gBias[x] = b0[x] + tv * W0[x * 65];
        gBias[256 + x] = b1[x] + tv * W1[x * 257];
        if (x < 64) gBias[512 + x] = b2[x] + tv * W2[x * 257];
    }
}

// ---------------- helpers ----------------
__device__ __forceinline__ u32 s2u(const void* p) {
    u32 a; asm("{.reg .u64 t; cvta.to.shared.u64 t,%1; cvt.u32.u64 %0,t;}" : "=r"(a) : "l"(p)); return a;
}
__device__ __forceinline__ void cp16(u32 s, const void* g) {
    asm volatile("cp.async.cg.shared.global [%0],[%1],16;" :: "r"(s), "l"(g));
}
__device__ __forceinline__ void ldsm4(u32* r, u32 a) {
    asm volatile("ldmatrix.sync.aligned.m8n8.x4.shared.b16 {%0,%1,%2,%3},[%4];"
        : "=r"(r[0]), "=r"(r[1]), "=r"(r[2]), "=r"(r[3]) : "r"(a));
}
__device__ __forceinline__ void ldsm2(u32* r, u32 a) {
    asm volatile("ldmatrix.sync.aligned.m8n8.x2.shared.b16 {%0,%1},[%2];"
        : "=r"(r[0]), "=r"(r[1]) : "r"(a));
}
__device__ __forceinline__ void mma16816(float* c, const u32* a, const u32* b) {
    asm volatile("mma.sync.aligned.m16n8k16.row.col.f32.bf16.bf16.f32 "
        "{%0,%1,%2,%3},{%4,%5,%6,%7},{%8,%9},{%0,%1,%2,%3};"
        : "+f"(c[0]), "+f"(c[1]), "+f"(c[2]), "+f"(c[3])
        : "r"(a[0]), "r"(a[1]), "r"(a[2]), "r"(a[3]), "r"(b[0]), "r"(b[1]));
}
__device__ __forceinline__ void actf(float z, float& s, float& h) {
    float ea  = __expf(-fabsf(z));
    float inv = __fdividef(1.f, 1.f + ea);
    s = (z >= 0.f) ? inv : ea * inv;
    h = fmaxf(z, 0.f) + __logf(1.f + ea);
}
__device__ __forceinline__ const unsigned char* chunk_src(int i, u32& sz) {
    if (i < 2)  { sz = 40960; return gImg + i * 40960; }
    if (i < 10) { sz = 40960; return gImg + 81920 + (i - 2) * 40960; }
    sz = 10240; return gImg + 409600 + (i - 10) * 10240;
}
// swizzled byte offset into activation plane: row stride 512B, 16B granule XOR
__device__ __forceinline__ u32 aoff(int row, int kb) {
    return (u32)row * 512u + ((((u32)kb >> 4) ^ (row & 7)) << 4) + (kb & 15);
}

__global__ void __launch_bounds__(256, 1)
odefunc_kernel(const float* __restrict__ y, const float* __restrict__ e,
               float* __restrict__ out)
{
    extern __shared__ char sm[];
    const u32 sb = s2u(sm);
    const int tid = threadIdx.x, lane = tid & 31, w = tid >> 5;
    const int mg = w >> 2, ng = w & 3;
    const size_t r0 = (size_t)blockIdx.x * 64;

    // ---- stage inputs: row 2b = y_state, row 2b+1 = e; bf16 hi/lo planes ----
    for (int p = tid; p < 4096; p += 256) {
        int m = p >> 5, kp = p & 31, b = m >> 1;
        float v0, v1;
        if (m & 1) { v0 = e[(r0 + b) * 64 + 2 * kp]; v1 = e[(r0 + b) * 64 + 2 * kp + 1]; }
        else       { v0 = y[(r0 + b) * 65 + 2 * kp]; v1 = y[(r0 + b) * 65 + 2 * kp + 1]; }
        __nv_bfloat162 hp, lp;
        hp.x = __float2bfloat16(v0); hp.y = __float2bfloat16(v1);
        lp.x = __float2bfloat16(v0 - __bfloat162float(hp.x));
        lp.y = __float2bfloat16(v1 - __bfloat162float(hp.y));
        u32 o = aoff(m, kp * 4);
        *(__nv_bfloat162*)(sm + o) = hp;
        *(__nv_bfloat162*)(sm + ALO + o) = lp;
    }
    for (int i = tid; i < 576; i += 256) ((float*)(sm + BIOFF))[i] = gBias[i];

    // prime chunk 0
    { u32 sz; const unsigned char* s = chunk_src(0, sz);
      for (u32 r = tid * 16; r < sz; r += 4096) cp16(sb + WOFF + r, s + r);
      asm volatile("cp.async.commit_group;"); }

    float acc[4][8][4];
    const float* bias = (const float*)(sm + BIOFF);
    const int g = lane >> 2, c2 = (lane & 3) * 2;
    const bool ev = !(g & 1);

    for (int c = 0; c < 18; c++) {
        if (c + 1 < 18) {
            u32 sz; const unsigned char* s = chunk_src(c + 1, sz);
            u32 dst = sb + WOFF + ((c + 1) & 1) * 40960u;
            for (u32 r = tid * 16; r < sz; r += 4096) cp16(dst + r, s + r);
            asm volatile("cp.async.commit_group;");
            asm volatile("cp.async.wait_group 1;" ::: "memory");
        } else {
            asm volatile("cp.async.wait_group 0;" ::: "memory");
        }
        __syncthreads();

        if (c == 0 || c == 2 || c == 10) {
#pragma unroll
            for (int mt = 0; mt < 4; mt++)
#pragma unroll
                for (int nt = 0; nt < 8; nt++)
#pragma unroll
                    for (int q = 0; q < 4; q++) acc[mt][nt][q] = 0.f;
        }

        // ---- consume chunk c (32 k = 2 mma k-steps) ----
        const int  lc  = (c < 2) ? c : ((c < 10) ? c - 2 : c - 10);
        const bool L2f = (c >= 10);
        const int  ntc = L2f ? 2 : 8;
        const u32  plb = L2f ? 5120u : 20480u;
        const u32  wb  = sb + WOFF + (c & 1) * 40960u;
        const int  nb0 = L2f ? ng * 16 : ng * 64;
#pragma unroll
        for (int ks = 0; ks < 2; ks++) {
            const int kb = lc * 64 + ks * 32;
            u32 af[4][2][4];
            {
                int arow = mg * 64 + (lane & 15);
                int akb  = kb + ((lane >> 4) << 4);
#pragma unroll
                for (int mt = 0; mt < 4; mt++) {
                    int row = arow + mt * 16;
                    u32 ad = sb + aoff(row, akb);
                    ldsm4(af[mt][0], ad);
                    ldsm4(af[mt][1], ad + ALO);
                }
            }
#pragma unroll
            for (int nt = 0; nt < 8; nt++) {
                if (nt >= ntc) break;
                int brow = nb0 + nt * 8 + (lane & 7);
                u32 bo = ks * 32 + ((lane >> 3) & 1) * 16;
                u32 bd = wb + brow * 80u + bo;
                u32 bh[2], bl[2];
                ldsm2(bh, bd); ldsm2(bl, bd + plb);
#pragma unroll
                for (int mt = 0; mt < 4; mt++) {
                    mma16816(acc[mt][nt], af[mt][0], bh);
                    mma16816(acc[mt][nt], af[mt][1], bh);
                    mma16816(acc[mt][nt], af[mt][0], bl);
                }
            }
        }
        __syncthreads();

        // ---- layer epilogues: softplus/JVP, write next activations ----
        if (c == 1 || c == 9) {
            const float* bs = bias + ((c == 1) ? 0 : 256);
#pragma unroll
            for (int mt = 0; mt < 4; mt++)
#pragma unroll
                for (int nt = 0; nt < 8; nt++) {
                    int n = ng * 64 + nt * 8 + c2;
                    float b0v = ev ? bs[n] : 0.f, b1v = ev ? bs[n + 1] : 0.f;
#pragma unroll
                    for (int h = 0; h < 2; h++) {
                        int row = mg * 64 + mt * 16 + g + h * 8;
                        float z0 = acc[mt][nt][2 * h]     + b0v;
                        float z1 = acc[mt][nt][2 * h + 1] + b1v;
                        float s0, h0, s1, h1;
                        actf(z0, s0, h0); actf(z1, s1, h1);
                        float su0 = __shfl_up_sync(0xffffffffu, s0, 4);
                        float su1 = __shfl_up_sync(0xffffffffu, s1, 4);
                        float v0 = ev ? h0 : su0 * z0;
                        float v1 = ev ? h1 : su1 * z1;
                        __nv_bfloat162 hp, lp;
                        hp.x = __float2bfloat16(v0); hp.y = __float2bfloat16(v1);
                        lp.x = __float2bfloat16(v0 - __bfloat162float(hp.x));
                        lp.y = __float2bfloat16(v1 - __bfloat162float(hp.y));
                        u32 o = aoff(row, 2 * n);
                        *(__nv_bfloat162*)(sm + o) = hp;
                        *(__nv_bfloat162*)(sm + ALO + o) = lp;
                    }
                }
            __syncthreads();
        }
    }

    // ---- final epilogue: dx (even rows) + divergence partials (odd rows) ----
    {
        const float* bs = bias + 512;
        float* dp = (float*)(sm + DIVOFF);
#pragma unroll
        for (int mt = 0; mt < 4; mt++)
#pragma unroll
            for (int h = 0; h < 2; h++) {
                int row = mg * 64 + mt * 16 + g + h * 8;
                int b = row >> 1;
                if (ev) {
#pragma unroll
                    for (int nt = 0; nt < 2; nt++) {
                        int n = ng * 16 + nt * 8 + c2;
                        out[(r0 + b) * 65 + n]     = acc[mt][nt][2 * h]     + bs[n];
                        out[(r0 + b) * 65 + n + 1] = acc[mt][nt][2 * h + 1] + bs[n + 1];
                    }
                } else {
                    float part = 0.f;
#pragma unroll
                    for (int nt = 0; nt < 2; nt++) {
                        int n = ng * 16 + nt * 8 + c2;
                        float2 ee = *(const float2*)&e[(r0 + b) * 64 + n];
                        part += acc[mt][nt][2 * h] * ee.x + acc[mt][nt][2 * h + 1] * ee.y;
                    }
                    dp[b * 16 + ng * 4 + (lane & 3)] = part;
                }
            }
    }
    __syncthreads();
    if (tid < 64) {
        const float* q = (const float*)(sm + DIVOFF) + tid * 16;
        float s = 0.f;
#pragma unroll
        for (int i = 0; i < 16; i++) s += q[i];
        out[(r0 + tid) * 65 + 64] = -s;
    }
}

// ---------------- launch ----------------
extern "C" void kernel_launch(void* const* d_in, const int* in_sizes, int n_in,
                              void* d_out, int out_size)
{
    const float* t  = (const float*)d_in[0];
    const float* y  = (const float*)d_in[1];
    const float* e  = (const float*)d_in[2];
    const float* W0 = (const float*)d_in[3];
    const float* b0 = (const float*)d_in[4];
    const float* W1 = (const float*)d_in[5];
    const float* b1 = (const float*)d_in[6];
    const float* W2 = (const float*)d_in[7];
    const float* b2 = (const float*)d_in[8];
    float* out = (float*)d_out;
    int B = in_sizes[1] / 65;

    cudaStreamCaptureStatus cs = cudaStreamCaptureStatusNone;
    cudaStreamIsCapturing((cudaStream_t)0, &cs);
    if (cs == cudaStreamCaptureStatusNone) {
        cudaFuncSetAttribute(odefunc_kernel,
                             cudaFuncAttributeMaxDynamicSharedMemorySize, SMEMSZ);
    }

    prep_kernel<<<256, 256>>>(t, W0, b0, W1, b1, W2, b2);
    odefunc_kernel<<<B / 64, 256, SMEMSZ>>>(y, e, out);
}

// round 11
// speedup vs baseline: 2.6322x; 1.1549x over previous
#include <cuda_runtime.h>
#include <cuda_bf16.h>
#include <cstdint>
typedef uint32_t u32;

// ---- smem byte map: A_hi[0,64K) A_lo[64K,128K) Wbuf[131072,+2x40960) bias, div ----
#define ALO    65536u
#define WOFF   131072u
#define BIOFF  212992u
#define DIVOFF 215296u
#define SMEMSZ 219392u

// 18 ldmatrix-ready weight chunk images: L0 2x40960, L1 8x40960, L2 8x10240
static __device__ __align__(16) unsigned char gImg[491520];
static __device__ float gBias[576];

__global__ void prep_kernel(const float* __restrict__ t,
                            const float* __restrict__ W0, const float* __restrict__ b0,
                            const float* __restrict__ W1, const float* __restrict__ b1,
                            const float* __restrict__ W2, const float* __restrict__ b2)
{
    int n = blockIdx.x, x = threadIdx.x;         // n: out-neuron, x: k
    {   // W1 [256][257]: chunks of 32 k, rows padded to 80B, hi then lo plane
        float v = W1[n * 257 + x + 1];
        __nv_bfloat16 h = __float2bfloat16(v);
        __nv_bfloat16 l = __float2bfloat16(v - __bfloat162float(h));
        u32 off = 81920u + (u32)(x >> 5) * 40960u + n * 80u + (x & 31) * 2u;
        *(__nv_bfloat16*)(gImg + off) = h;
        *(__nv_bfloat16*)(gImg + off + 20480u) = l;
    }
    if (x < 64) {   // W0 [256][65], K=64 -> 2 chunks
        float v = W0[n * 65 + x + 1];
        __nv_bfloat16 h = __float2bfloat16(v);
        __nv_bfloat16 l = __float2bfloat16(v - __bfloat162float(h));
        u32 off = (u32)(x >> 5) * 40960u + n * 80u + (x & 31) * 2u;
        *(__nv_bfloat16*)(gImg + off) = h;
        *(__nv_bfloat16*)(gImg + off + 20480u) = l;
    }
    if (n < 64) {   // W2 [64][257], 64 rows -> 8 chunks of 10240
        float v = W2[n * 257 + x + 1];
        __nv_bfloat16 h = __float2bfloat16(v);
        __nv_bfloat16 l = __float2bfloat16(v - __bfloat162float(h));
        u32 off = 409600u + (u32)(x >> 5) * 10240u + n * 80u + (x & 31) * 2u;
        *(__nv_bfloat16*)(gImg + off) = h;
        *(__nv_bfloat16*)(gImg + off + 5120u) = l;
    }
    if (n == 0) {
        float tv = t[0];
        gBias[x] = b0[x] + tv * W0[x * 65];
        gBias[256 + x] = b1[x] + tv * W1[x * 257];
        if (x < 64) gBias[512 + x] = b2[x] + tv * W2[x * 257];
    }
}

// ---------------- helpers ----------------
__device__ __forceinline__ u32 s2u(const void* p) {
    u32 a; asm("{.reg .u64 t; cvta.to.shared.u64 t,%1; cvt.u32.u64 %0,t;}" : "=r"(a) : "l"(p)); return a;
}
__device__ __forceinline__ void cp16(u32 s, const void* g) {
    asm volatile("cp.async.cg.shared.global [%0],[%1],16;" :: "r"(s), "l"(g));
}
__device__ __forceinline__ void ldsm4(u32* r, u32 a) {
    asm volatile("ldmatrix.sync.aligned.m8n8.x4.shared.b16 {%0,%1,%2,%3},[%4];"
        : "=r"(r[0]), "=r"(r[1]), "=r"(r[2]), "=r"(r[3]) : "r"(a));
}
__device__ __forceinline__ void ldsm2(u32* r, u32 a) {
    asm volatile("ldmatrix.sync.aligned.m8n8.x2.shared.b16 {%0,%1},[%2];"
        : "=r"(r[0]), "=r"(r[1]) : "r"(a));
}
__device__ __forceinline__ void mma16816(float* c, const u32* a, const u32* b) {
    asm volatile("mma.sync.aligned.m16n8k16.row.col.f32.bf16.bf16.f32 "
        "{%0,%1,%2,%3},{%4,%5,%6,%7},{%8,%9},{%0,%1,%2,%3};"
        : "+f"(c[0]), "+f"(c[1]), "+f"(c[2]), "+f"(c[3])
        : "r"(a[0]), "r"(a[1]), "r"(a[2]), "r"(a[3]), "r"(b[0]), "r"(b[1]));
}
__device__ __forceinline__ void actf(float z, float& s, float& h) {
    float ea  = __expf(-fabsf(z));
    float inv = __fdividef(1.f, 1.f + ea);
    s = (z >= 0.f) ? inv : ea * inv;
    h = fmaxf(z, 0.f) + __logf(1.f + ea);
}
__device__ __forceinline__ const unsigned char* chunk_src(int i, u32& sz) {
    if (i < 2)  { sz = 40960; return gImg + i * 40960; }
    if (i < 10) { sz = 40960; return gImg + 81920 + (i - 2) * 40960; }
    sz = 10240; return gImg + 409600 + (i - 10) * 10240;
}
// swizzled byte offset into activation plane: row stride 512B, 16B granule XOR
__device__ __forceinline__ u32 aoff(int row, int kb) {
    return (u32)row * 512u + ((((u32)kb >> 4) ^ (row & 7)) << 4) + (kb & 15);
}

__global__ void __launch_bounds__(512, 1)
odefunc_kernel(const float* __restrict__ y, const float* __restrict__ e,
               float* __restrict__ out)
{
    extern __shared__ char sm[];
    const u32 sb = s2u(sm);
    const int tid = threadIdx.x, lane = tid & 31, w = tid >> 5;
    const int mg = w >> 2, ng = w & 3;          // 4 x 4 warp grid
    const size_t r0 = (size_t)blockIdx.x * 64;

    // ---- stage inputs: row 2b = y_state, row 2b+1 = e; bf16 hi/lo planes ----
    for (int p = tid; p < 4096; p += 512) {
        int m = p >> 5, kp = p & 31, b = m >> 1;
        float v0, v1;
        if (m & 1) { v0 = e[(r0 + b) * 64 + 2 * kp]; v1 = e[(r0 + b) * 64 + 2 * kp + 1]; }
        else       { v0 = y[(r0 + b) * 65 + 2 * kp]; v1 = y[(r0 + b) * 65 + 2 * kp + 1]; }
        __nv_bfloat162 hp, lp;
        hp.x = __float2bfloat16(v0); hp.y = __float2bfloat16(v1);
        lp.x = __float2bfloat16(v0 - __bfloat162float(hp.x));
        lp.y = __float2bfloat16(v1 - __bfloat162float(hp.y));
        u32 o = aoff(m, kp * 4);
        *(__nv_bfloat162*)(sm + o) = hp;
        *(__nv_bfloat162*)(sm + ALO + o) = lp;
    }
    for (int i = tid; i < 576; i += 512) ((float*)(sm + BIOFF))[i] = gBias[i];

    // prime chunk 0
    { u32 sz; const unsigned char* s = chunk_src(0, sz);
      for (u32 r = tid * 16; r < sz; r += 8192) cp16(sb + WOFF + r, s + r);
      asm volatile("cp.async.commit_group;"); }

    float acc[2][8][4];
    const float* bias = (const float*)(sm + BIOFF);
    const int g = lane >> 2, c2 = (lane & 3) * 2;
    const bool ev = !(g & 1);

    for (int c = 0; c < 18; c++) {
        if (c + 1 < 18) {
            u32 sz; const unsigned char* s = chunk_src(c + 1, sz);
            u32 dst = sb + WOFF + ((c + 1) & 1) * 40960u;
            for (u32 r = tid * 16; r < sz; r += 8192) cp16(dst + r, s + r);
            asm volatile("cp.async.commit_group;");
            asm volatile("cp.async.wait_group 1;" ::: "memory");
        } else {
            asm volatile("cp.async.wait_group 0;" ::: "memory");
        }
        __syncthreads();

        if (c == 0 || c == 2 || c == 10) {
#pragma unroll
            for (int mt = 0; mt < 2; mt++)
#pragma unroll
                for (int nt = 0; nt < 8; nt++)
#pragma unroll
                    for (int q = 0; q < 4; q++) acc[mt][nt][q] = 0.f;
        }

        // ---- consume chunk c (32 k = 2 mma k-steps) ----
        const int  lc  = (c < 2) ? c : ((c < 10) ? c - 2 : c - 10);
        const bool L2f = (c >= 10);
        const int  ntc = L2f ? 2 : 8;
        const u32  plb = L2f ? 5120u : 20480u;
        const u32  wb  = sb + WOFF + (c & 1) * 40960u;
        const int  nb0 = L2f ? ng * 16 : ng * 64;
#pragma unroll
        for (int ks = 0; ks < 2; ks++) {
            const int kb = lc * 64 + ks * 32;
            u32 af[2][2][4];
            {
                int arow = mg * 32 + (lane & 15);
                int akb  = kb + ((lane >> 4) << 4);
#pragma unroll
                for (int mt = 0; mt < 2; mt++) {
                    int row = arow + mt * 16;
                    u32 ad = sb + aoff(row, akb);
                    ldsm4(af[mt][0], ad);
                    ldsm4(af[mt][1], ad + ALO);
                }
            }
#pragma unroll
            for (int nt = 0; nt < 8; nt++) {
                if (nt >= ntc) break;
                int brow = nb0 + nt * 8 + (lane & 7);
                u32 bo = ks * 32 + ((lane >> 3) & 1) * 16;
                u32 bd = wb + brow * 80u + bo;
                u32 bh[2], bl[2];
                ldsm2(bh, bd); ldsm2(bl, bd + plb);
#pragma unroll
                for (int mt = 0; mt < 2; mt++) {
                    mma16816(acc[mt][nt], af[mt][0], bh);
                    mma16816(acc[mt][nt], af[mt][1], bh);
                    mma16816(acc[mt][nt], af[mt][0], bl);
                }
            }
        }
        __syncthreads();

        // ---- layer epilogues: softplus/JVP, write next activations ----
        if (c == 1 || c == 9) {
            const float* bs = bias + ((c == 1) ? 0 : 256);
#pragma unroll
            for (int mt = 0; mt < 2; mt++)
#pragma unroll
                for (int nt = 0; nt < 8; nt++) {
                    int n = ng * 64 + nt * 8 + c2;
                    float b0v = ev ? bs[n] : 0.f, b1v = ev ? bs[n + 1] : 0.f;
#pragma unroll
                    for (int h = 0; h < 2; h++) {
                        int row = mg * 32 + mt * 16 + g + h * 8;
                        float z0 = acc[mt][nt][2 * h]     + b0v;
                        float z1 = acc[mt][nt][2 * h + 1] + b1v;
                        float s0, h0, s1, h1;
                        actf(z0, s0, h0); actf(z1, s1, h1);
                        float su0 = __shfl_up_sync(0xffffffffu, s0, 4);
                        float su1 = __shfl_up_sync(0xffffffffu, s1, 4);
                        float v0 = ev ? h0 : su0 * z0;
                        float v1 = ev ? h1 : su1 * z1;
                        __nv_bfloat162 hp, lp;
                        hp.x = __float2bfloat16(v0); hp.y = __float2bfloat16(v1);
                        lp.x = __float2bfloat16(v0 - __bfloat162float(hp.x));
                        lp.y = __float2bfloat16(v1 - __bfloat162float(hp.y));
                        u32 o = aoff(row, 2 * n);
                        *(__nv_bfloat162*)(sm + o) = hp;
                        *(__nv_bfloat162*)(sm + ALO + o) = lp;
                    }
                }
            __syncthreads();
        }
    }

    // ---- final epilogue: dx (even rows) + divergence partials (odd rows) ----
    {
        const float* bs = bias + 512;
        float* dp = (float*)(sm + DIVOFF);
#pragma unroll
        for (int mt = 0; mt < 2; mt++)
#pragma unroll
            for (int h = 0; h < 2; h++) {
                int row = mg * 32 + mt * 16 + g + h * 8;
                int b = row >> 1;
                if (ev) {
#pragma unroll
                    for (int nt = 0; nt < 2; nt++) {
                        int n = ng * 16 + nt * 8 + c2;
                        out[(r0 + b) * 65 + n]     = acc[mt][nt][2 * h]     + bs[n];
                        out[(r0 + b) * 65 + n + 1] = acc[mt][nt][2 * h + 1] + bs[n + 1];
                    }
                } else {
                    float part = 0.f;
#pragma unroll
                    for (int nt = 0; nt < 2; nt++) {
                        int n = ng * 16 + nt * 8 + c2;
                        float2 ee = *(const float2*)&e[(r0 + b) * 64 + n];
                        part += acc[mt][nt][2 * h] * ee.x + acc[mt][nt][2 * h + 1] * ee.y;
                    }
                    dp[b * 16 + ng * 4 + (lane & 3)] = part;
                }
            }
    }
    __syncthreads();
    if (tid < 64) {
        const float* q = (const float*)(sm + DIVOFF) + tid * 16;
        float s = 0.f;
#pragma unroll
        for (int i = 0; i < 16; i++) s += q[i];
        out[(r0 + tid) * 65 + 64] = -s;
    }
}

// ---------------- launch ----------------
extern "C" void kernel_launch(void* const* d_in, const int* in_sizes, int n_in,
                              void* d_out, int out_size)
{
    const float* t  = (const float*)d_in[0];
    const float* y  = (const float*)d_in[1];
    const float* e  = (const float*)d_in[2];
    const float* W0 = (const float*)d_in[3];
    const float* b0 = (const float*)d_in[4];
    const float* W1 = (const float*)d_in[5];
    const float* b1 = (const float*)d_in[6];
    const float* W2 = (const float*)d_in[7];
    const float* b2 = (const float*)d_in[8];
    float* out = (float*)d_out;
    int B = in_sizes[1] / 65;

    cudaStreamCaptureStatus cs = cudaStreamCaptureStatusNone;
    cudaStreamIsCapturing((cudaStream_t)0, &cs);
    if (cs == cudaStreamCaptureStatusNone) {
        cudaFuncSetAttribute(odefunc_kernel,
                             cudaFuncAttributeMaxDynamicSharedMemorySize, SMEMSZ);
    }

    prep_kernel<<<256, 256>>>(t, W0, b0, W1, b1, W2, b2);
    odefunc_kernel<<<B / 64, 512, SMEMSZ>>>(y, e, out);
}